// round 14
// baseline (speedup 1.0000x reference)
#include <cuda_runtime.h>

typedef unsigned long long u64;

// ---- packed f32x2 helpers (sm_103a packed fp32 pipe) ----
__device__ __forceinline__ u64 pk2(float l, float h) {
    u64 r; asm("mov.b64 %0, {%1,%2};" : "=l"(r) : "f"(l), "f"(h)); return r;
}
__device__ __forceinline__ u64 pkb(float w) { return pk2(w, w); }
__device__ __forceinline__ void upk(u64 v, float& l, float& h) {
    asm("mov.b64 {%0,%1}, %2;" : "=f"(l), "=f"(h) : "l"(v));
}
__device__ __forceinline__ u64 fma2(u64 a, u64 b, u64 c) {
    u64 d; asm("fma.rn.f32x2 %0, %1, %2, %3;" : "=l"(d) : "l"(a), "l"(b), "l"(c)); return d;
}
__device__ __forceinline__ u64 add2(u64 a, u64 b) {
    u64 d; asm("add.rn.f32x2 %0, %1, %2;" : "=l"(d) : "l"(a), "l"(b)); return d;
}
__device__ __forceinline__ u64 mul2(u64 a, u64 b) {
    u64 d; asm("mul.rn.f32x2 %0, %1, %2;" : "=l"(d) : "l"(a), "l"(b)); return d;
}

#define KDUP(bits) ((((u64)(bits)) << 32) | (u64)(bits))
static constexpr u64 K06  = KDUP(0x3F19999Au);  // 0.6f
static constexpr u64 K04  = KDUP(0x3ECCCCCDu);  // 0.4f
static constexpr u64 KABS = 0x7FFFFFFF7FFFFFFFull;

__device__ __forceinline__ u64 leaky2(u64 v) {
    return fma2(v & KABS, K04, mul2(v, K06));
}

__device__ __forceinline__ u64 tanh2(u64 v) {
    float l, h; upk(v, l, h);
    float tl, th;
    asm("tanh.approx.f32 %0, %1;" : "=f"(tl) : "f"(l));
    asm("tanh.approx.f32 %0, %1;" : "=f"(th) : "f"(h));
    return pk2(tl, th);
}

__device__ __forceinline__ ulonglong2 lds2(const u64* p) {
    return *reinterpret_cast<const ulonglong2*>(p);
}

__global__ void __launch_bounds__(128, 4)
minigen_kernel(const float4* __restrict__ x,
               const float* __restrict__ w_enc1, const float* __restrict__ b_enc1,
               const float* __restrict__ w_bneck, const float* __restrict__ b_bneck,
               const float* __restrict__ w_dec1, const float* __restrict__ b_dec1,
               const float* __restrict__ w_out,  const float* __restrict__ b_out,
               float4* __restrict__ out)
{
    // weights pre-duplicated u64, 16B-aligned quads (as R12)
    __shared__ __align__(16) u64 s_we[32];    // per c: {w00,w01,w02,w10,w11,w12,bias,pad}
    __shared__ __align__(16) u64 s_wb[128];   // per co: {w[0..11], bias, pad x3}
    __shared__ __align__(16) u64 s_wdf[128];  // per (c,ci): {w0, w2, w0+w1, w1+w2}
    __shared__ __align__(16) u64 s_wof[32];   // per (c,ci): same fold
    __shared__ __align__(16) u64 s_bd[4], s_bo[2];
    // per-thread scratch: 16 ulonglong2 slots (= 32 u64 = E or S), thread-strided
    __shared__ __align__(16) ulonglong2 scratch[16 * 128];

    int t = threadIdx.x;
    if (t < 4) {
        #pragma unroll
        for (int j = 0; j < 6; j++) s_we[t*8 + j] = pkb(w_enc1[t*6 + j]);
        s_we[t*8 + 6] = pkb(b_enc1[t]);
        s_we[t*8 + 7] = 0;
        s_bd[t] = pkb(b_dec1[t]);
    }
    if (t >= 8 && t < 16) {
        int co = t - 8;
        #pragma unroll
        for (int j = 0; j < 12; j++) s_wb[co*16 + j] = pkb(w_bneck[co*12 + j]);
        s_wb[co*16 + 12] = pkb(b_bneck[co]);
        s_wb[co*16 + 13] = 0; s_wb[co*16 + 14] = 0; s_wb[co*16 + 15] = 0;
    }
    if (t >= 32 && t < 64) {
        int p = t - 32;
        float w0 = w_dec1[p*3], w1 = w_dec1[p*3+1], w2 = w_dec1[p*3+2];
        s_wdf[p*4+0] = pkb(w0);      s_wdf[p*4+1] = pkb(w2);
        s_wdf[p*4+2] = pkb(w0 + w1); s_wdf[p*4+3] = pkb(w1 + w2);
    }
    if (t >= 64 && t < 72) {
        int p = t - 64;
        float w0 = w_out[p*3], w1 = w_out[p*3+1], w2 = w_out[p*3+2];
        s_wof[p*4+0] = pkb(w0);      s_wof[p*4+1] = pkb(w2);
        s_wof[p*4+2] = pkb(w0 + w1); s_wof[p*4+3] = pkb(w1 + w2);
    }
    if (t >= 72 && t < 74) s_bo[t - 72] = pkb(b_out[t - 72]);
    __syncthreads();

    ulonglong2* scr = &scratch[t];            // slot j at scr[j*128]
    int i = blockIdx.x * blockDim.x + t;      // sample-pair index
    const float4* xp = x + (size_t)i * 16;

    u64 E[4][8];

    // ===== enc1, first half: input pos 0..7 -> E[:][0..3] =====
    u64 P0[8], P1[8];
    {
        float4 a, b;
        a = xp[0]; b = xp[8];
        P0[0]=pk2(a.x,b.x); P0[1]=pk2(a.y,b.y); P0[2]=pk2(a.z,b.z); P0[3]=pk2(a.w,b.w);
        a = xp[1]; b = xp[9];
        P0[4]=pk2(a.x,b.x); P0[5]=pk2(a.y,b.y); P0[6]=pk2(a.z,b.z); P0[7]=pk2(a.w,b.w);
        a = xp[4]; b = xp[12];
        P1[0]=pk2(a.x,b.x); P1[1]=pk2(a.y,b.y); P1[2]=pk2(a.z,b.z); P1[3]=pk2(a.w,b.w);
        a = xp[5]; b = xp[13];
        P1[4]=pk2(a.x,b.x); P1[5]=pk2(a.y,b.y); P1[6]=pk2(a.z,b.z); P1[7]=pk2(a.w,b.w);
    }
    #pragma unroll
    for (int c = 0; c < 4; c++) {
        ulonglong2 q0 = lds2(&s_we[c*8 + 0]);
        ulonglong2 q1 = lds2(&s_we[c*8 + 2]);
        ulonglong2 q2 = lds2(&s_we[c*8 + 4]);
        u64 w00 = q0.x, w01 = q0.y, w02 = q1.x;
        u64 w10 = q1.y, w11 = q2.x, w12 = q2.y;
        u64 b2 = s_we[c*8 + 6];
        #pragma unroll
        for (int l = 0; l < 4; l++) {
            int p = 2 * l;
            u64 a = b2;
            if (l > 0) { a = fma2(w00, P0[p-1], a); a = fma2(w10, P1[p-1], a); }
            a = fma2(w01, P0[p],   a); a = fma2(w11, P1[p],   a);
            a = fma2(w02, P0[p+1], a); a = fma2(w12, P1[p+1], a);
            E[c][l] = leaky2(a);
        }
    }
    u64 k0 = P0[7], k1 = P1[7];   // pos-7 halo

    // ===== enc1, second half: input pos 8..15 -> E[:][4..7] =====
    {
        float4 a, b;
        a = xp[2]; b = xp[10];
        P0[0]=pk2(a.x,b.x); P0[1]=pk2(a.y,b.y); P0[2]=pk2(a.z,b.z); P0[3]=pk2(a.w,b.w);
        a = xp[3]; b = xp[11];
        P0[4]=pk2(a.x,b.x); P0[5]=pk2(a.y,b.y); P0[6]=pk2(a.z,b.z); P0[7]=pk2(a.w,b.w);
        a = xp[6]; b = xp[14];
        P1[0]=pk2(a.x,b.x); P1[1]=pk2(a.y,b.y); P1[2]=pk2(a.z,b.z); P1[3]=pk2(a.w,b.w);
        a = xp[7]; b = xp[15];
        P1[4]=pk2(a.x,b.x); P1[5]=pk2(a.y,b.y); P1[6]=pk2(a.z,b.z); P1[7]=pk2(a.w,b.w);
    }
    #pragma unroll
    for (int c = 0; c < 4; c++) {
        ulonglong2 q0 = lds2(&s_we[c*8 + 0]);
        ulonglong2 q1 = lds2(&s_we[c*8 + 2]);
        ulonglong2 q2 = lds2(&s_we[c*8 + 4]);
        u64 w00 = q0.x, w01 = q0.y, w02 = q1.x;
        u64 w10 = q1.y, w11 = q2.x, w12 = q2.y;
        u64 b2 = s_we[c*8 + 6];
        {
            u64 a = b2;
            a = fma2(w00, k0,    a); a = fma2(w10, k1,    a);
            a = fma2(w01, P0[0], a); a = fma2(w11, P1[0], a);
            a = fma2(w02, P0[1], a); a = fma2(w12, P1[1], a);
            E[c][4] = leaky2(a);
        }
        #pragma unroll
        for (int l = 5; l < 8; l++) {
            int p = 2 * l - 8;
            u64 a = b2;
            a = fma2(w00, P0[p-1], a); a = fma2(w10, P1[p-1], a);
            a = fma2(w01, P0[p],   a); a = fma2(w11, P1[p],   a);
            a = fma2(w02, P0[p+1], a); a = fma2(w12, P1[p+1], a);
            E[c][l] = leaky2(a);
        }
    }
    // P0/P1 dead. Stash E for the skip connection (slot c*4+q = pair E[c][2q],E[c][2q+1])
    #pragma unroll
    for (int c = 0; c < 4; c++)
        #pragma unroll
        for (int q = 0; q < 4; q++)
            scr[(c*4 + q) * 128] = make_ulonglong2(E[c][2*q], E[c][2*q+1]);

    // ===== bneck, phase A: Bn[:][0..1] (reads E[:][0..3]) =====
    u64 Bn[8][4];
    #pragma unroll
    for (int co = 0; co < 8; co++) {
        u64 a0 = s_wb[co*16 + 12], a1 = a0;
        #pragma unroll
        for (int ci = 0; ci < 4; ci++) {
            ulonglong2 qa = lds2(&s_wb[co*16 + ci*3 + (ci & 1)]);   // not aligned-safe; load scalars instead
            (void)qa;
            u64 w0 = s_wb[co*16 + ci*3 + 0];
            u64 w1 = s_wb[co*16 + ci*3 + 1];
            u64 w2 = s_wb[co*16 + ci*3 + 2];
            a0 = fma2(w1, E[ci][0], a0); a0 = fma2(w2, E[ci][1], a0);
            a1 = fma2(w0, E[ci][1], a1); a1 = fma2(w1, E[ci][2], a1); a1 = fma2(w2, E[ci][3], a1);
        }
        Bn[co][0] = leaky2(a0); Bn[co][1] = leaky2(a1);
    }
    // ===== bneck, phase B: Bn[:][2..3] (reads E[:][3..7]; E[:][0..2] dead) =====
    #pragma unroll
    for (int co = 0; co < 8; co++) {
        u64 a2 = s_wb[co*16 + 12], a3 = a2;
        #pragma unroll
        for (int ci = 0; ci < 4; ci++) {
            u64 w0 = s_wb[co*16 + ci*3 + 0];
            u64 w1 = s_wb[co*16 + ci*3 + 1];
            u64 w2 = s_wb[co*16 + ci*3 + 2];
            a2 = fma2(w0, E[ci][3], a2); a2 = fma2(w1, E[ci][4], a2); a2 = fma2(w2, E[ci][5], a2);
            a3 = fma2(w0, E[ci][5], a3); a3 = fma2(w1, E[ci][6], a3); a3 = fma2(w2, E[ci][7], a3);
        }
        Bn[co][2] = leaky2(a2); Bn[co][3] = leaky2(a3);
    }
    // E register copies dead past here (skip copy lives in scratch).

    // ===== dec1 in position halves; S streamed to scratch (overwrites E slots) =====
    // half A: l = 0..3  (uses Bn[ci][0..2])
    #pragma unroll
    for (int c = 0; c < 4; c++) {
        u64 b2 = s_bd[c];
        u64 a0 = b2, a1 = b2, a2 = b2, a3 = b2;
        #pragma unroll
        for (int ci = 0; ci < 8; ci++) {
            ulonglong2 qa = lds2(&s_wdf[(c*8 + ci)*4 + 0]);  // w0, w2
            ulonglong2 qb = lds2(&s_wdf[(c*8 + ci)*4 + 2]);  // w01, w12
            u64 w0 = qa.x, w2 = qa.y, w01 = qb.x, w12 = qb.y;
            u64 q0 = Bn[ci][0], q1 = Bn[ci][1], q2 = Bn[ci][2];
            a0 = fma2(w12, q0, a0);
            a1 = fma2(w01, q0, a1); a1 = fma2(w2,  q1, a1);
            a2 = fma2(w0,  q0, a2); a2 = fma2(w12, q1, a2);
            a3 = fma2(w01, q1, a3); a3 = fma2(w2,  q2, a3);
        }
        ulonglong2 e0 = scr[(c*4 + 0) * 128];
        ulonglong2 e1 = scr[(c*4 + 1) * 128];
        scr[(c*4 + 0) * 128] = make_ulonglong2(add2(leaky2(a0), e0.x), add2(leaky2(a1), e0.y));
        scr[(c*4 + 1) * 128] = make_ulonglong2(add2(leaky2(a2), e1.x), add2(leaky2(a3), e1.y));
    }
    // half B: l = 4..7  (uses Bn[ci][1..3])
    #pragma unroll
    for (int c = 0; c < 4; c++) {
        u64 b2 = s_bd[c];
        u64 a4 = b2, a5 = b2, a6 = b2, a7 = b2;
        #pragma unroll
        for (int ci = 0; ci < 8; ci++) {
            ulonglong2 qa = lds2(&s_wdf[(c*8 + ci)*4 + 0]);
            ulonglong2 qb = lds2(&s_wdf[(c*8 + ci)*4 + 2]);
            u64 w0 = qa.x, w2 = qa.y, w01 = qb.x, w12 = qb.y;
            u64 q1 = Bn[ci][1], q2 = Bn[ci][2], q3 = Bn[ci][3];
            a4 = fma2(w0,  q1, a4); a4 = fma2(w12, q2, a4);
            a5 = fma2(w01, q2, a5); a5 = fma2(w2,  q3, a5);
            a6 = fma2(w0,  q2, a6); a6 = fma2(w12, q3, a6);
            a7 = fma2(w01, q3, a7);
        }
        ulonglong2 e2 = scr[(c*4 + 2) * 128];
        ulonglong2 e3 = scr[(c*4 + 3) * 128];
        scr[(c*4 + 2) * 128] = make_ulonglong2(add2(leaky2(a4), e2.x), add2(leaky2(a5), e2.y));
        scr[(c*4 + 3) * 128] = make_ulonglong2(add2(leaky2(a6), e3.x), add2(leaky2(a7), e3.y));
    }
    // Bn dead past here. Scratch now holds S[4][8].

    // ===== out: upsample2 + conv(C4->C2, k3, s1, p1) + tanh =====
    u64 oacc[2][16];
    {
        u64 b0 = s_bo[0], b1 = s_bo[1];
        #pragma unroll
        for (int l = 0; l < 16; l++) { oacc[0][l] = b0; oacc[1][l] = b1; }
    }
    #pragma unroll
    for (int ci = 0; ci < 4; ci++) {
        ulonglong2 s01 = scr[(ci*4 + 0) * 128];
        ulonglong2 s23 = scr[(ci*4 + 1) * 128];
        ulonglong2 s45 = scr[(ci*4 + 2) * 128];
        ulonglong2 s67 = scr[(ci*4 + 3) * 128];
        u64 S0 = s01.x, S1 = s01.y, S2 = s23.x, S3 = s23.y;
        u64 S4 = s45.x, S5 = s45.y, S6 = s67.x, S7 = s67.y;
        #pragma unroll
        for (int c = 0; c < 2; c++) {
            ulonglong2 qa = lds2(&s_wof[(c*4 + ci)*4 + 0]);  // w0, w2
            ulonglong2 qb = lds2(&s_wof[(c*4 + ci)*4 + 2]);  // w01, w12
            u64 w0 = qa.x, w2 = qa.y, w01 = qb.x, w12 = qb.y;
            u64* A = oacc[c];
            A[0]  = fma2(w12, S0, A[0]);
            A[1]  = fma2(w01, S0, A[1]);  A[1]  = fma2(w2,  S1, A[1]);
            A[2]  = fma2(w0,  S0, A[2]);  A[2]  = fma2(w12, S1, A[2]);
            A[3]  = fma2(w01, S1, A[3]);  A[3]  = fma2(w2,  S2, A[3]);
            A[4]  = fma2(w0,  S1, A[4]);  A[4]  = fma2(w12, S2, A[4]);
            A[5]  = fma2(w01, S2, A[5]);  A[5]  = fma2(w2,  S3, A[5]);
            A[6]  = fma2(w0,  S2, A[6]);  A[6]  = fma2(w12, S3, A[6]);
            A[7]  = fma2(w01, S3, A[7]);  A[7]  = fma2(w2,  S4, A[7]);
            A[8]  = fma2(w0,  S3, A[8]);  A[8]  = fma2(w12, S4, A[8]);
            A[9]  = fma2(w01, S4, A[9]);  A[9]  = fma2(w2,  S5, A[9]);
            A[10] = fma2(w0,  S4, A[10]); A[10] = fma2(w12, S5, A[10]);
            A[11] = fma2(w01, S5, A[11]); A[11] = fma2(w2,  S6, A[11]);
            A[12] = fma2(w0,  S5, A[12]); A[12] = fma2(w12, S6, A[12]);
            A[13] = fma2(w01, S6, A[13]); A[13] = fma2(w2,  S7, A[13]);
            A[14] = fma2(w0,  S6, A[14]); A[14] = fma2(w12, S7, A[14]);
            A[15] = fma2(w01, S7, A[15]);
        }
    }

    float4* op = out + (size_t)i * 16;
    #pragma unroll
    for (int c = 0; c < 2; c++) {
        #pragma unroll
        for (int q = 0; q < 4; q++) {
            u64 t0 = tanh2(oacc[c][q*4+0]);
            u64 t1 = tanh2(oacc[c][q*4+1]);
            u64 t2 = tanh2(oacc[c][q*4+2]);
            u64 t3 = tanh2(oacc[c][q*4+3]);
            float4 va, vb;
            upk(t0, va.x, vb.x); upk(t1, va.y, vb.y);
            upk(t2, va.z, vb.z); upk(t3, va.w, vb.w);
            op[c*4 + q]     = va;
            op[8 + c*4 + q] = vb;
        }
    }
}

extern "C" void kernel_launch(void* const* d_in, const int* in_sizes, int n_in,
                              void* d_out, int out_size) {
    const float4* x      = (const float4*)d_in[0];
    const float* w_enc1  = (const float*)d_in[1];
    const float* b_enc1  = (const float*)d_in[2];
    const float* w_bneck = (const float*)d_in[3];
    const float* b_bneck = (const float*)d_in[4];
    const float* w_dec1  = (const float*)d_in[5];
    const float* b_dec1  = (const float*)d_in[6];
    const float* w_out   = (const float*)d_in[7];
    const float* b_out   = (const float*)d_in[8];
    float4* out = (float4*)d_out;

    int B = in_sizes[0] / 32;        // samples
    int pairs = B / 2;               // two samples per thread
    int threads = 128;
    int blocks = (pairs + threads - 1) / threads;
    minigen_kernel<<<blocks, threads>>>(x, w_enc1, b_enc1, w_bneck, b_bneck,
                                        w_dec1, b_dec1, w_out, b_out, out);
}

// round 15
// speedup vs baseline: 1.4932x; 1.4932x over previous
#include <cuda_runtime.h>

#define SLOPE 0.2f

// leaky(x) = 0.6x + 0.4|x|  (2 FMA-pipe ops, branch-free)
__device__ __forceinline__ float leaky(float v) {
    return fmaf(0.4f, fabsf(v), 0.6f * v);
}

// HW tanh (sm_75+ MUFU.TANH): 1 op
__device__ __forceinline__ float fast_tanh(float x) {
    float r;
    asm("tanh.approx.f32 %0, %1;" : "=f"(r) : "f"(x));
    return r;
}

__global__ void __launch_bounds__(128)
minigen_kernel(const float4* __restrict__ x,
               const float* __restrict__ w_enc1, const float* __restrict__ b_enc1,
               const float* __restrict__ w_bneck, const float* __restrict__ b_bneck,
               const float* __restrict__ w_dec1, const float* __restrict__ b_dec1,
               const float* __restrict__ w_out,  const float* __restrict__ b_out,
               float4* __restrict__ out)
{
    // weight layouts sized for float4 (LDS.128) loads
    __shared__ __align__(16) float s_we[4][8];    // {w00,w01,w02,w10,w11,w12,bias,pad}
    __shared__ __align__(16) float s_wb[8][16];   // {w[0..11], bias, pad x3}
    __shared__ __align__(16) float s_wdf[32][4];  // per (c*8+ci): {w0, w2, w0+w1, w1+w2}
    __shared__ __align__(16) float s_wof[8][4];   // per (c*4+ci): same fold
    __shared__ float s_bd[4], s_bo[2];

    int t = threadIdx.x;
    if (t < 4) {
        #pragma unroll
        for (int j = 0; j < 6; j++) s_we[t][j] = w_enc1[t*6 + j];
        s_we[t][6] = b_enc1[t];
        s_we[t][7] = 0.0f;
        s_bd[t] = b_dec1[t];
    }
    if (t >= 8 && t < 16) {
        int co = t - 8;
        #pragma unroll
        for (int j = 0; j < 12; j++) s_wb[co][j] = w_bneck[co*12 + j];
        s_wb[co][12] = b_bneck[co];
        s_wb[co][13] = s_wb[co][14] = s_wb[co][15] = 0.0f;
    }
    if (t >= 32 && t < 64) {
        int p = t - 32;   // c*8 + ci
        float w0 = w_dec1[p*3], w1 = w_dec1[p*3+1], w2 = w_dec1[p*3+2];
        s_wdf[p][0] = w0;      s_wdf[p][1] = w2;
        s_wdf[p][2] = w0 + w1; s_wdf[p][3] = w1 + w2;
    }
    if (t >= 64 && t < 72) {
        int p = t - 64;   // c*4 + ci
        float w0 = w_out[p*3], w1 = w_out[p*3+1], w2 = w_out[p*3+2];
        s_wof[p][0] = w0;      s_wof[p][1] = w2;
        s_wof[p][2] = w0 + w1; s_wof[p][3] = w1 + w2;
    }
    if (t >= 72 && t < 74) s_bo[t - 72] = b_out[t - 72];
    __syncthreads();

    int i = blockIdx.x * blockDim.x + t;          // sample index
    const float4* xp = x + (size_t)i * 8;

    float E[4][8];

    // ===== enc1 first half: input pos 0..7 (both channels) -> E[:][0..3] =====
    float P0[8], P1[8];
    {
        float4 v;
        v = xp[0]; P0[0]=v.x; P0[1]=v.y; P0[2]=v.z; P0[3]=v.w;
        v = xp[1]; P0[4]=v.x; P0[5]=v.y; P0[6]=v.z; P0[7]=v.w;
        v = xp[4]; P1[0]=v.x; P1[1]=v.y; P1[2]=v.z; P1[3]=v.w;
        v = xp[5]; P1[4]=v.x; P1[5]=v.y; P1[6]=v.z; P1[7]=v.w;
    }
    #pragma unroll
    for (int c = 0; c < 4; c++) {
        float4 wa = *reinterpret_cast<const float4*>(&s_we[c][0]);  // w00,w01,w02,w10
        float4 wb = *reinterpret_cast<const float4*>(&s_we[c][4]);  // w11,w12,bias,pad
        float w00 = wa.x, w01 = wa.y, w02 = wa.z, w10 = wa.w;
        float w11 = wb.x, w12 = wb.y, bb = wb.z;
        #pragma unroll
        for (int l = 0; l < 4; l++) {
            int p = 2 * l;
            float a = bb;
            if (l > 0) { a = fmaf(w00, P0[p-1], a); a = fmaf(w10, P1[p-1], a); }
            a = fmaf(w01, P0[p],   a); a = fmaf(w11, P1[p],   a);
            a = fmaf(w02, P0[p+1], a); a = fmaf(w12, P1[p+1], a);
            E[c][l] = leaky(a);
        }
    }
    float k0 = P0[7], k1 = P1[7];   // pos-7 halo

    // ===== enc1 second half: input pos 8..15 -> E[:][4..7] =====
    {
        float4 v;
        v = xp[2]; P0[0]=v.x; P0[1]=v.y; P0[2]=v.z; P0[3]=v.w;
        v = xp[3]; P0[4]=v.x; P0[5]=v.y; P0[6]=v.z; P0[7]=v.w;
        v = xp[6]; P1[0]=v.x; P1[1]=v.y; P1[2]=v.z; P1[3]=v.w;
        v = xp[7]; P1[4]=v.x; P1[5]=v.y; P1[6]=v.z; P1[7]=v.w;
    }
    #pragma unroll
    for (int c = 0; c < 4; c++) {
        float4 wa = *reinterpret_cast<const float4*>(&s_we[c][0]);
        float4 wb = *reinterpret_cast<const float4*>(&s_we[c][4]);
        float w00 = wa.x, w01 = wa.y, w02 = wa.z, w10 = wa.w;
        float w11 = wb.x, w12 = wb.y, bb = wb.z;
        {
            float a = bb;
            a = fmaf(w00, k0,    a); a = fmaf(w10, k1,    a);
            a = fmaf(w01, P0[0], a); a = fmaf(w11, P1[0], a);
            a = fmaf(w02, P0[1], a); a = fmaf(w12, P1[1], a);
            E[c][4] = leaky(a);
        }
        #pragma unroll
        for (int l = 5; l < 8; l++) {
            int p = 2 * l - 8;
            float a = bb;
            a = fmaf(w00, P0[p-1], a); a = fmaf(w10, P1[p-1], a);
            a = fmaf(w01, P0[p],   a); a = fmaf(w11, P1[p],   a);
            a = fmaf(w02, P0[p+1], a); a = fmaf(w12, P1[p+1], a);
            E[c][l] = leaky(a);
        }
    }
    // P0/P1 dead past here.

    // ===== bneck: conv(C4->C8, k3, s2, p1) + leaky -> Bn[8][4] =====
    float Bn[8][4];
    #pragma unroll
    for (int co = 0; co < 8; co++) {
        float4 q0 = *reinterpret_cast<const float4*>(&s_wb[co][0]);   // w0..w3
        float4 q1 = *reinterpret_cast<const float4*>(&s_wb[co][4]);   // w4..w7
        float4 q2 = *reinterpret_cast<const float4*>(&s_wb[co][8]);   // w8..w11
        float bb = s_wb[co][12];
        float wk[12] = {q0.x,q0.y,q0.z,q0.w, q1.x,q1.y,q1.z,q1.w, q2.x,q2.y,q2.z,q2.w};
        float a0 = bb, a1 = bb, a2 = bb, a3 = bb;
        #pragma unroll
        for (int ci = 0; ci < 4; ci++) {
            float w0 = wk[ci*3], w1 = wk[ci*3+1], w2 = wk[ci*3+2];
            a0 = fmaf(w1, E[ci][0], a0); a0 = fmaf(w2, E[ci][1], a0);
            a1 = fmaf(w0, E[ci][1], a1); a1 = fmaf(w1, E[ci][2], a1); a1 = fmaf(w2, E[ci][3], a1);
            a2 = fmaf(w0, E[ci][3], a2); a2 = fmaf(w1, E[ci][4], a2); a2 = fmaf(w2, E[ci][5], a2);
            a3 = fmaf(w0, E[ci][5], a3); a3 = fmaf(w1, E[ci][6], a3); a3 = fmaf(w2, E[ci][7], a3);
        }
        Bn[co][0] = leaky(a0); Bn[co][1] = leaky(a1);
        Bn[co][2] = leaky(a2); Bn[co][3] = leaky(a3);
    }

    // ===== dec1: upsample2 + conv(C8->C4, k3, s1, p1) + leaky, skip in-place into E =====
    #pragma unroll
    for (int c = 0; c < 4; c++) {
        float acc[8];
        float bb = s_bd[c];
        #pragma unroll
        for (int l = 0; l < 8; l++) acc[l] = bb;
        #pragma unroll
        for (int ci = 0; ci < 8; ci++) {
            float4 wf = *reinterpret_cast<const float4*>(&s_wdf[c*8 + ci][0]);  // w0,w2,w01,w12
            float w0 = wf.x, w2 = wf.y, w01 = wf.z, w12 = wf.w;
            float q0 = Bn[ci][0], q1 = Bn[ci][1], q2 = Bn[ci][2], q3 = Bn[ci][3];
            acc[0] = fmaf(w12, q0, acc[0]);
            acc[1] = fmaf(w01, q0, acc[1]); acc[1] = fmaf(w2,  q1, acc[1]);
            acc[2] = fmaf(w0,  q0, acc[2]); acc[2] = fmaf(w12, q1, acc[2]);
            acc[3] = fmaf(w01, q1, acc[3]); acc[3] = fmaf(w2,  q2, acc[3]);
            acc[4] = fmaf(w0,  q1, acc[4]); acc[4] = fmaf(w12, q2, acc[4]);
            acc[5] = fmaf(w01, q2, acc[5]); acc[5] = fmaf(w2,  q3, acc[5]);
            acc[6] = fmaf(w0,  q2, acc[6]); acc[6] = fmaf(w12, q3, acc[6]);
            acc[7] = fmaf(w01, q3, acc[7]);
        }
        #pragma unroll
        for (int l = 0; l < 8; l++)
            E[c][l] = leaky(acc[l]) + E[c][l];   // skip connection -> S
    }
    // Bn dead past here. E now holds S.

    // ===== out: upsample2 + conv(C4->C2, k3, s1, p1) + tanh; store per channel =====
    float4* op = out + (size_t)i * 8;
    #pragma unroll
    for (int c = 0; c < 2; c++) {
        float acc[16];
        float bb = s_bo[c];
        #pragma unroll
        for (int l = 0; l < 16; l++) acc[l] = bb;
        #pragma unroll
        for (int ci = 0; ci < 4; ci++) {
            float4 wf = *reinterpret_cast<const float4*>(&s_wof[c*4 + ci][0]);  // w0,w2,w01,w12
            float w0 = wf.x, w2 = wf.y, w01 = wf.z, w12 = wf.w;
            float S0 = E[ci][0], S1 = E[ci][1], S2 = E[ci][2], S3 = E[ci][3];
            float S4 = E[ci][4], S5 = E[ci][5], S6 = E[ci][6], S7 = E[ci][7];
            acc[0]  = fmaf(w12, S0, acc[0]);
            acc[1]  = fmaf(w01, S0, acc[1]);  acc[1]  = fmaf(w2,  S1, acc[1]);
            acc[2]  = fmaf(w0,  S0, acc[2]);  acc[2]  = fmaf(w12, S1, acc[2]);
            acc[3]  = fmaf(w01, S1, acc[3]);  acc[3]  = fmaf(w2,  S2, acc[3]);
            acc[4]  = fmaf(w0,  S1, acc[4]);  acc[4]  = fmaf(w12, S2, acc[4]);
            acc[5]  = fmaf(w01, S2, acc[5]);  acc[5]  = fmaf(w2,  S3, acc[5]);
            acc[6]  = fmaf(w0,  S2, acc[6]);  acc[6]  = fmaf(w12, S3, acc[6]);
            acc[7]  = fmaf(w01, S3, acc[7]);  acc[7]  = fmaf(w2,  S4, acc[7]);
            acc[8]  = fmaf(w0,  S3, acc[8]);  acc[8]  = fmaf(w12, S4, acc[8]);
            acc[9]  = fmaf(w01, S4, acc[9]);  acc[9]  = fmaf(w2,  S5, acc[9]);
            acc[10] = fmaf(w0,  S4, acc[10]); acc[10] = fmaf(w12, S5, acc[10]);
            acc[11] = fmaf(w01, S5, acc[11]); acc[11] = fmaf(w2,  S6, acc[11]);
            acc[12] = fmaf(w0,  S5, acc[12]); acc[12] = fmaf(w12, S6, acc[12]);
            acc[13] = fmaf(w01, S6, acc[13]); acc[13] = fmaf(w2,  S7, acc[13]);
            acc[14] = fmaf(w0,  S6, acc[14]); acc[14] = fmaf(w12, S7, acc[14]);
            acc[15] = fmaf(w01, S7, acc[15]);
        }
        #pragma unroll
        for (int q = 0; q < 4; q++) {
            float4 v;
            v.x = fast_tanh(acc[q*4+0]);
            v.y = fast_tanh(acc[q*4+1]);
            v.z = fast_tanh(acc[q*4+2]);
            v.w = fast_tanh(acc[q*4+3]);
            op[c*4 + q] = v;
        }
    }
}

extern "C" void kernel_launch(void* const* d_in, const int* in_sizes, int n_in,
                              void* d_out, int out_size) {
    const float4* x      = (const float4*)d_in[0];
    const float* w_enc1  = (const float*)d_in[1];
    const float* b_enc1  = (const float*)d_in[2];
    const float* w_bneck = (const float*)d_in[3];
    const float* b_bneck = (const float*)d_in[4];
    const float* w_dec1  = (const float*)d_in[5];
    const float* b_dec1  = (const float*)d_in[6];
    const float* w_out   = (const float*)d_in[7];
    const float* b_out   = (const float*)d_in[8];
    float4* out = (float4*)d_out;

    int B = in_sizes[0] / 32;        // samples, one per thread
    int threads = 128;
    int blocks = (B + threads - 1) / threads;
    minigen_kernel<<<blocks, threads>>>(x, w_enc1, b_enc1, w_bneck, b_bneck,
                                        w_dec1, b_dec1, w_out, b_out, out);
}

// round 17
// speedup vs baseline: 1.9670x; 1.3173x over previous
#include <cuda_runtime.h>

// leaky(x) = 0.6x + 0.4|x| (branch-free)
__device__ __forceinline__ float leaky(float v) {
    return fmaf(0.4f, fabsf(v), 0.6f * v);
}

__device__ __forceinline__ float fast_tanh(float x) {
    float r;
    asm("tanh.approx.f32 %0, %1;" : "=f"(r) : "f"(x));
    return r;
}

// smem tile: 128 samples/block, row stride 9 float4 (36 floats) -> conflict-free
#define ROWQ 9

__global__ void __launch_bounds__(128)
minigen_kernel(const float4* __restrict__ x,
               const float* __restrict__ w_enc1, const float* __restrict__ b_enc1,
               const float* __restrict__ w_bneck, const float* __restrict__ b_bneck,
               const float* __restrict__ w_dec1, const float* __restrict__ b_dec1,
               const float* __restrict__ w_out,  const float* __restrict__ b_out,
               float4* __restrict__ out)
{
    __shared__ __align__(16) float s_we[4][8];    // {w00,w01,w02,w10,w11,w12,bias,pad}
    __shared__ __align__(16) float s_wb[8][16];   // {w[0..11], bias, pad x3}
    __shared__ __align__(16) float s_wdf[32][4];  // {w0, w2, w0+w1, w1+w2}
    __shared__ __align__(16) float s_wof[8][4];
    __shared__ float s_bd[4], s_bo[2];
    __shared__ __align__(16) float4 sbuf[128 * ROWQ];   // 18 KB staging tile

    int t = threadIdx.x;
    if (t < 4) {
        #pragma unroll
        for (int j = 0; j < 6; j++) s_we[t][j] = w_enc1[t*6 + j];
        s_we[t][6] = b_enc1[t];
        s_we[t][7] = 0.0f;
        s_bd[t] = b_dec1[t];
    }
    if (t >= 8 && t < 16) {
        int co = t - 8;
        #pragma unroll
        for (int j = 0; j < 12; j++) s_wb[co][j] = w_bneck[co*12 + j];
        s_wb[co][12] = b_bneck[co];
        s_wb[co][13] = s_wb[co][14] = s_wb[co][15] = 0.0f;
    }
    if (t >= 32 && t < 64) {
        int p = t - 32;   // c*8 + ci
        float w0 = w_dec1[p*3], w1 = w_dec1[p*3+1], w2 = w_dec1[p*3+2];
        s_wdf[p][0] = w0;      s_wdf[p][1] = w2;
        s_wdf[p][2] = w0 + w1; s_wdf[p][3] = w1 + w2;
    }
    if (t >= 64 && t < 72) {
        int p = t - 64;   // c*4 + ci
        float w0 = w_out[p*3], w1 = w_out[p*3+1], w2 = w_out[p*3+2];
        s_wof[p][0] = w0;      s_wof[p][1] = w2;
        s_wof[p][2] = w0 + w1; s_wof[p][3] = w1 + w2;
    }
    if (t >= 72 && t < 74) s_bo[t - 72] = b_out[t - 72];

    // ===== coalesced input staging: 1024 float4 tile -> padded smem rows =====
    {
        const float4* gx = x + (size_t)blockIdx.x * 1024;
        #pragma unroll
        for (int k = 0; k < 8; k++) {
            int g = k * 128 + t;                 // consecutive lanes -> consecutive 16B
            float4 v = gx[g];
            sbuf[(g >> 3) * ROWQ + (g & 7)] = v;
        }
    }
    __syncthreads();

    float E[4][8];
    const float4* row = &sbuf[t * ROWQ];

    // ===== enc1 first half: input pos 0..7 -> E[:][0..3] =====
    float P0[8], P1[8];
    {
        float4 v;
        v = row[0]; P0[0]=v.x; P0[1]=v.y; P0[2]=v.z; P0[3]=v.w;
        v = row[1]; P0[4]=v.x; P0[5]=v.y; P0[6]=v.z; P0[7]=v.w;
        v = row[4]; P1[0]=v.x; P1[1]=v.y; P1[2]=v.z; P1[3]=v.w;
        v = row[5]; P1[4]=v.x; P1[5]=v.y; P1[6]=v.z; P1[7]=v.w;
    }
    #pragma unroll
    for (int c = 0; c < 4; c++) {
        float4 wa = *reinterpret_cast<const float4*>(&s_we[c][0]);
        float4 wb = *reinterpret_cast<const float4*>(&s_we[c][4]);
        float w00 = wa.x, w01 = wa.y, w02 = wa.z, w10 = wa.w;
        float w11 = wb.x, w12 = wb.y, bb = wb.z;
        #pragma unroll
        for (int l = 0; l < 4; l++) {
            int p = 2 * l;
            float a = bb;
            if (l > 0) { a = fmaf(w00, P0[p-1], a); a = fmaf(w10, P1[p-1], a); }
            a = fmaf(w01, P0[p],   a); a = fmaf(w11, P1[p],   a);
            a = fmaf(w02, P0[p+1], a); a = fmaf(w12, P1[p+1], a);
            E[c][l] = leaky(a);
        }
    }
    float k0 = P0[7], k1 = P1[7];   // pos-7 halo

    // ===== enc1 second half: input pos 8..15 -> E[:][4..7] =====
    {
        float4 v;
        v = row[2]; P0[0]=v.x; P0[1]=v.y; P0[2]=v.z; P0[3]=v.w;
        v = row[3]; P0[4]=v.x; P0[5]=v.y; P0[6]=v.z; P0[7]=v.w;
        v = row[6]; P1[0]=v.x; P1[1]=v.y; P1[2]=v.z; P1[3]=v.w;
        v = row[7]; P1[4]=v.x; P1[5]=v.y; P1[6]=v.z; P1[7]=v.w;
    }
    #pragma unroll
    for (int c = 0; c < 4; c++) {
        float4 wa = *reinterpret_cast<const float4*>(&s_we[c][0]);
        float4 wb = *reinterpret_cast<const float4*>(&s_we[c][4]);
        float w00 = wa.x, w01 = wa.y, w02 = wa.z, w10 = wa.w;
        float w11 = wb.x, w12 = wb.y, bb = wb.z;
        {
            float a = bb;
            a = fmaf(w00, k0,    a); a = fmaf(w10, k1,    a);
            a = fmaf(w01, P0[0], a); a = fmaf(w11, P1[0], a);
            a = fmaf(w02, P0[1], a); a = fmaf(w12, P1[1], a);
            E[c][4] = leaky(a);
        }
        #pragma unroll
        for (int l = 5; l < 8; l++) {
            int p = 2 * l - 8;
            float a = bb;
            a = fmaf(w00, P0[p-1], a); a = fmaf(w10, P1[p-1], a);
            a = fmaf(w01, P0[p],   a); a = fmaf(w11, P1[p],   a);
            a = fmaf(w02, P0[p+1], a); a = fmaf(w12, P1[p+1], a);
            E[c][l] = leaky(a);
        }
    }
    // P0/P1 dead past here; thread t's input rows dead (only thread t read them).

    // ===== bneck: conv(C4->C8, k3, s2, p1) + leaky -> Bn[8][4] =====
    float Bn[8][4];
    #pragma unroll
    for (int co = 0; co < 8; co++) {
        float4 q0 = *reinterpret_cast<const float4*>(&s_wb[co][0]);
        float4 q1 = *reinterpret_cast<const float4*>(&s_wb[co][4]);
        float4 q2 = *reinterpret_cast<const float4*>(&s_wb[co][8]);
        float bb = s_wb[co][12];
        float wk[12] = {q0.x,q0.y,q0.z,q0.w, q1.x,q1.y,q1.z,q1.w, q2.x,q2.y,q2.z,q2.w};
        float a0 = bb, a1 = bb, a2 = bb, a3 = bb;
        #pragma unroll
        for (int ci = 0; ci < 4; ci++) {
            float w0 = wk[ci*3], w1 = wk[ci*3+1], w2 = wk[ci*3+2];
            a0 = fmaf(w1, E[ci][0], a0); a0 = fmaf(w2, E[ci][1], a0);
            a1 = fmaf(w0, E[ci][1], a1); a1 = fmaf(w1, E[ci][2], a1); a1 = fmaf(w2, E[ci][3], a1);
            a2 = fmaf(w0, E[ci][3], a2); a2 = fmaf(w1, E[ci][4], a2); a2 = fmaf(w2, E[ci][5], a2);
            a3 = fmaf(w0, E[ci][5], a3); a3 = fmaf(w1, E[ci][6], a3); a3 = fmaf(w2, E[ci][7], a3);
        }
        Bn[co][0] = leaky(a0); Bn[co][1] = leaky(a1);
        Bn[co][2] = leaky(a2); Bn[co][3] = leaky(a3);
    }

    // ===== dec1: upsample2 + conv(C8->C4) + leaky, skip in-place into E =====
    #pragma unroll
    for (int c = 0; c < 4; c++) {
        float acc[8];
        float bb = s_bd[c];
        #pragma unroll
        for (int l = 0; l < 8; l++) acc[l] = bb;
        #pragma unroll
        for (int ci = 0; ci < 8; ci++) {
            float4 wf = *reinterpret_cast<const float4*>(&s_wdf[c*8 + ci][0]);
            float w0 = wf.x, w2 = wf.y, w01 = wf.z, w12 = wf.w;
            float q0 = Bn[ci][0], q1 = Bn[ci][1], q2 = Bn[ci][2], q3 = Bn[ci][3];
            acc[0] = fmaf(w12, q0, acc[0]);
            acc[1] = fmaf(w01, q0, acc[1]); acc[1] = fmaf(w2,  q1, acc[1]);
            acc[2] = fmaf(w0,  q0, acc[2]); acc[2] = fmaf(w12, q1, acc[2]);
            acc[3] = fmaf(w01, q1, acc[3]); acc[3] = fmaf(w2,  q2, acc[3]);
            acc[4] = fmaf(w0,  q1, acc[4]); acc[4] = fmaf(w12, q2, acc[4]);
            acc[5] = fmaf(w01, q2, acc[5]); acc[5] = fmaf(w2,  q3, acc[5]);
            acc[6] = fmaf(w0,  q2, acc[6]); acc[6] = fmaf(w12, q3, acc[6]);
            acc[7] = fmaf(w01, q3, acc[7]);
        }
        #pragma unroll
        for (int l = 0; l < 8; l++)
            E[c][l] = leaky(acc[l]) + E[c][l];   // skip -> S
    }
    // Bn dead. E holds S.

    // ===== out layer + tanh; stage to own smem row =====
    float4* wrow = &sbuf[t * ROWQ];
    #pragma unroll
    for (int c = 0; c < 2; c++) {
        float acc[16];
        float bb = s_bo[c];
        #pragma unroll
        for (int l = 0; l < 16; l++) acc[l] = bb;
        #pragma unroll
        for (int ci = 0; ci < 4; ci++) {
            float4 wf = *reinterpret_cast<const float4*>(&s_wof[c*4 + ci][0]);
            float w0 = wf.x, w2 = wf.y, w01 = wf.z, w12 = wf.w;
            float S0 = E[ci][0], S1 = E[ci][1], S2 = E[ci][2], S3 = E[ci][3];
            float S4 = E[ci][4], S5 = E[ci][5], S6 = E[ci][6], S7 = E[ci][7];
            acc[0]  = fmaf(w12, S0, acc[0]);
            acc[1]  = fmaf(w01, S0, acc[1]);  acc[1]  = fmaf(w2,  S1, acc[1]);
            acc[2]  = fmaf(w0,  S0, acc[2]);  acc[2]  = fmaf(w12, S1, acc[2]);
            acc[3]  = fmaf(w01, S1, acc[3]);  acc[3]  = fmaf(w2,  S2, acc[3]);
            acc[4]  = fmaf(w0,  S1, acc[4]);  acc[4]  = fmaf(w12, S2, acc[4]);
            acc[5]  = fmaf(w01, S2, acc[5]);  acc[5]  = fmaf(w2,  S3, acc[5]);
            acc[6]  = fmaf(w0,  S2, acc[6]);  acc[6]  = fmaf(w12, S3, acc[6]);
            acc[7]  = fmaf(w01, S3, acc[7]);  acc[7]  = fmaf(w2,  S4, acc[7]);
            acc[8]  = fmaf(w0,  S3, acc[8]);  acc[8]  = fmaf(w12, S4, acc[8]);
            acc[9]  = fmaf(w01, S4, acc[9]);  acc[9]  = fmaf(w2,  S5, acc[9]);
            acc[10] = fmaf(w0,  S4, acc[10]); acc[10] = fmaf(w12, S5, acc[10]);
            acc[11] = fmaf(w01, S5, acc[11]); acc[11] = fmaf(w2,  S6, acc[11]);
            acc[12] = fmaf(w0,  S5, acc[12]); acc[12] = fmaf(w12, S6, acc[12]);
            acc[13] = fmaf(w01, S6, acc[13]); acc[13] = fmaf(w2,  S7, acc[13]);
            acc[14] = fmaf(w0,  S6, acc[14]); acc[14] = fmaf(w12, S7, acc[14]);
            acc[15] = fmaf(w01, S7, acc[15]);
        }
        #pragma unroll
        for (int q = 0; q < 4; q++) {
            float4 v;
            v.x = fast_tanh(acc[q*4+0]);
            v.y = fast_tanh(acc[q*4+1]);
            v.z = fast_tanh(acc[q*4+2]);
            v.w = fast_tanh(acc[q*4+3]);
            wrow[c*4 + q] = v;
        }
    }
    __syncthreads();

    // ===== coalesced output: padded smem rows -> global =====
    {
        float4* gout = out + (size_t)blockIdx.x * 1024;
        #pragma unroll
        for (int k = 0; k < 8; k++) {
            int g = k * 128 + t;
            gout[g] = sbuf[(g >> 3) * ROWQ + (g & 7)];
        }
    }
}

extern "C" void kernel_launch(void* const* d_in, const int* in_sizes, int n_in,
                              void* d_out, int out_size) {
    const float4* x      = (const float4*)d_in[0];
    const float* w_enc1  = (const float*)d_in[1];
    const float* b_enc1  = (const float*)d_in[2];
    const float* w_bneck = (const float*)d_in[3];
    const float* b_bneck = (const float*)d_in[4];
    const float* w_dec1  = (const float*)d_in[5];
    const float* b_dec1  = (const float*)d_in[6];
    const float* w_out   = (const float*)d_in[7];
    const float* b_out   = (const float*)d_in[8];
    float4* out = (float4*)d_out;

    int B = in_sizes[0] / 32;        // samples, one per thread
    int threads = 128;
    int blocks = (B + threads - 1) / threads;
    minigen_kernel<<<blocks, threads>>>(x, w_enc1, b_enc1, w_bneck, b_bneck,
                                        w_dec1, b_dec1, w_out, b_out, out);
}